// round 1
// baseline (speedup 1.0000x reference)
#include <cuda_runtime.h>

#define NN 256
#define PCOUNT 16
#define CH 20
#define TILE 32

// Effective 5x5 kernels (padded to 28 floats per (p,k) for float4 LDS) + biases
__device__ float gE[144 * 28];
__device__ float gB[144];

// ---------------------------------------------------------------------------
// Kernel 1: compose W1 (1->20, 3x3) with W2 (20->9, 3x3) into effective 5x5
// E[p,k][u][v] = sum_c sum_{a+b=u-wise} W1[p,c,a] * W2[p,k,c,b]
// B[p,k] = b2[p,k] + sum_c b1[p,c] * sum_b W2[p,k,c,b]
// ---------------------------------------------------------------------------
__global__ void k_precompute(const float* __restrict__ W1, const float* __restrict__ b1,
                             const float* __restrict__ W2, const float* __restrict__ b2) {
    int t = threadIdx.x;
    if (t >= 144) return;
    int p = t / 9, k = t % 9;
    float e[25];
#pragma unroll
    for (int i = 0; i < 25; i++) e[i] = 0.f;
    float bacc = 0.f;
    for (int c = 0; c < CH; c++) {
        float w1[9];
        const float* w1p = W1 + (p * CH + c) * 9;
#pragma unroll
        for (int a = 0; a < 9; a++) w1[a] = w1p[a];
        const float* w2p = W2 + ((p * 9 + k) * CH + c) * 9;
        float s2 = 0.f;
#pragma unroll
        for (int bq = 0; bq < 9; bq++) {
            float w2 = w2p[bq];
            s2 += w2;
            int by = bq / 3, bx = bq % 3;
#pragma unroll
            for (int a = 0; a < 9; a++) {
                int ay = a / 3, ax = a % 3;
                e[(ay + by) * 5 + (ax + bx)] += w1[a] * w2;
            }
        }
        bacc += s2 * b1[p * CH + c];
    }
#pragma unroll
    for (int i = 0; i < 25; i++) gE[t * 28 + i] = e[i];
    gE[t * 28 + 25] = 0.f; gE[t * 28 + 26] = 0.f; gE[t * 28 + 27] = 0.f;
    gB[t] = b2[t] + bacc;
}

// ---------------------------------------------------------------------------
// Kernel 2: main fused kernel (exact for all pixels not on the outermost ring).
// Per pixel: K[p,k] = B[p,k] + 5x5 conv of img with E[p,k];
//            y[b,i]  = sum_{j,k} K[i*4+j, k] * x[b,j] patch
// 32x32 tile, 256 threads, 4 vertical pixels/thread (amortizes E broadcasts).
// Border pixels are written as 0 (border kernel atomically adds exact value).
// ---------------------------------------------------------------------------
__global__ void __launch_bounds__(256, 2) k_main(const float* __restrict__ img,
                                                 const float* __restrict__ x,
                                                 float* __restrict__ y) {
    __shared__ __align__(16) float sE[144 * 28];
    __shared__ float sB[144];
    __shared__ float sImg[36 * 36];
    __shared__ float sX[4][34 * 34];

    const int b  = blockIdx.z;
    const int n0 = blockIdx.y * TILE;
    const int m0 = blockIdx.x * TILE;
    const int t  = threadIdx.x;

    for (int i = t; i < 144 * 28; i += 256) sE[i] = gE[i];
    if (t < 144) sB[t] = gB[t];

    const float* imgb = img + b * NN * NN;
    for (int i = t; i < 36 * 36; i += 256) {
        int r = i / 36, c = i % 36;
        int gn = n0 + r - 2, gm = m0 + c - 2;
        float v = 0.f;
        if ((unsigned)gn < NN && (unsigned)gm < NN) v = __ldg(imgb + gn * NN + gm);
        sImg[i] = v;
    }
#pragma unroll
    for (int j = 0; j < 4; j++) {
        const float* xb = x + ((b * 4 + j) * NN) * NN;
        for (int i = t; i < 34 * 34; i += 256) {
            int r = i / 34, c = i % 34;
            int gn = n0 + r - 1, gm = m0 + c - 1;
            float v = 0.f;
            if ((unsigned)gn < NN && (unsigned)gm < NN) v = __ldg(xb + gn * NN + gm);
            sX[j][i] = v;
        }
    }
    __syncthreads();

    const int tx = t & 31;
    const int r0 = (t >> 5) * 4;   // local row base, 4 contiguous rows per thread

    // img patch: rows r0..r0+7, cols tx..tx+4 (pixel (r0+px,tx) needs img[+u-2,+v-2])
    float ip[8][5];
#pragma unroll
    for (int r = 0; r < 8; r++)
#pragma unroll
        for (int v = 0; v < 5; v++)
            ip[r][v] = sImg[(r0 + r) * 36 + tx + v];

    float acc[4][4];
#pragma unroll
    for (int i = 0; i < 4; i++)
#pragma unroll
        for (int px = 0; px < 4; px++) acc[i][px] = 0.f;

#pragma unroll 1
    for (int j = 0; j < 4; j++) {
        const float* sxj = sX[j];
#pragma unroll
        for (int i = 0; i < 4; i++) {
            const int p = i * 4 + j;
            const float* Ep = sE + p * 9 * 28;
            const float* Bp = sB + p * 9;
#pragma unroll 1
            for (int k = 0; k < 9; k++) {
                float bq = Bp[k];
                float kv0 = bq, kv1 = bq, kv2 = bq, kv3 = bq;
                const float4* ev = reinterpret_cast<const float4*>(Ep + k * 28);
                float er[28];
#pragma unroll
                for (int q = 0; q < 7; q++) {
                    float4 t4 = ev[q];
                    er[q * 4 + 0] = t4.x; er[q * 4 + 1] = t4.y;
                    er[q * 4 + 2] = t4.z; er[q * 4 + 3] = t4.w;
                }
#pragma unroll
                for (int u = 0; u < 5; u++)
#pragma unroll
                    for (int v = 0; v < 5; v++) {
                        float e = er[u * 5 + v];
                        kv0 += e * ip[0 + u][v];
                        kv1 += e * ip[1 + u][v];
                        kv2 += e * ip[2 + u][v];
                        kv3 += e * ip[3 + u][v];
                    }
                int di = k / 3;
                int dj = k - di * 3;
                int xo = (r0 + di) * 34 + tx + dj;
                float xv0 = sxj[xo];
                float xv1 = sxj[xo + 34];
                float xv2 = sxj[xo + 68];
                float xv3 = sxj[xo + 102];
                acc[i][0] += kv0 * xv0;
                acc[i][1] += kv1 * xv1;
                acc[i][2] += kv2 * xv2;
                acc[i][3] += kv3 * xv3;
            }
        }
    }

    const int gm = m0 + tx;
#pragma unroll
    for (int i = 0; i < 4; i++) {
        float* yb = y + (((b * 4 + i) * NN) + n0 + r0) * NN + gm;
#pragma unroll
        for (int px = 0; px < 4; px++) {
            int gn = n0 + r0 + px;
            bool bord = (gn == 0) | (gn == NN - 1) | (gm == 0) | (gm == NN - 1);
            yb[px * NN] = bord ? 0.f : acc[i][px];
        }
    }
}

// ---------------------------------------------------------------------------
// Kernel 3: exact two-conv evaluation on the 1-pixel border ring.
// Block = (p, pixel-chunk). Each thread handles one (border-pixel, p) pair,
// computes exact K[p, 0..8] (zero-padded h at out-of-grid positions) and
// atomically adds its (i=p/4, j=p%4) contribution into y (pre-zeroed by k_main).
// ---------------------------------------------------------------------------
__global__ void __launch_bounds__(256) k_border(const float* __restrict__ img,
                                                const float* __restrict__ x,
                                                const float* __restrict__ W1,
                                                const float* __restrict__ b1,
                                                const float* __restrict__ W2,
                                                const float* __restrict__ b2,
                                                float* __restrict__ y) {
    __shared__ float sW1[180];
    __shared__ float sb1[20];
    __shared__ float sW2[1620];
    __shared__ float sb2[9];

    const int p = blockIdx.x;
    const int t = threadIdx.x;
    for (int i = t; i < 180; i += 256) sW1[i] = W1[p * 180 + i];
    for (int i = t; i < 1620; i += 256) sW2[i] = W2[p * 1620 + i];
    if (t < 20) sb1[t] = b1[p * 20 + t];
    if (t < 9)  sb2[t] = b2[p * 9 + t];
    __syncthreads();

    int idx = blockIdx.y * 256 + t;
    if (idx >= 4080) return;                 // 4 batches x 1020 ring pixels
    int b = idx / 1020;
    int r = idx % 1020;
    int n, m;
    if (r < 256)       { n = 0;   m = r; }
    else if (r < 512)  { n = 255; m = r - 256; }
    else { int r2 = r - 512; n = 1 + (r2 >> 1); m = (r2 & 1) ? 255 : 0; }

    const float* imgb = img + b * NN * NN;
    float ipat[25];
#pragma unroll
    for (int u = 0; u < 5; u++)
#pragma unroll
        for (int v = 0; v < 5; v++) {
            int gn = n + u - 2, gm = m + v - 2;
            ipat[u * 5 + v] = ((unsigned)gn < NN && (unsigned)gm < NN)
                              ? __ldg(imgb + gn * NN + gm) : 0.f;
        }

    float hmask[9];
#pragma unroll
    for (int q = 0; q < 9; q++) {
        int qy = q / 3, qx = q % 3;
        int hn = n + qy - 1, hm = m + qx - 1;
        hmask[q] = ((unsigned)hn < NN && (unsigned)hm < NN) ? 1.f : 0.f;
    }

    float K[9];
#pragma unroll
    for (int k = 0; k < 9; k++) K[k] = sb2[k];

#pragma unroll 1
    for (int c = 0; c < CH; c++) {
        float h[9];
#pragma unroll
        for (int q = 0; q < 9; q++) {
            int qy = q / 3, qx = q % 3;
            float s = sb1[c];
#pragma unroll
            for (int a = 0; a < 9; a++) {
                int ay = a / 3, ax = a % 3;
                s += sW1[c * 9 + a] * ipat[(qy + ay) * 5 + (qx + ax)];
            }
            h[q] = s * hmask[q];
        }
#pragma unroll
        for (int k = 0; k < 9; k++)
#pragma unroll
            for (int q = 0; q < 9; q++)
                K[k] += sW2[(k * CH + c) * 9 + q] * h[q];
    }

    const int i = p >> 2, j = p & 3;
    const float* xb = x + ((b * 4 + j) * NN) * NN;
    float s = 0.f;
#pragma unroll
    for (int k = 0; k < 9; k++) {
        int di = k / 3, dj = k % 3;
        int gn = n + di - 1, gm = m + dj - 1;
        float xv = ((unsigned)gn < NN && (unsigned)gm < NN)
                   ? __ldg(xb + gn * NN + gm) : 0.f;
        s += K[k] * xv;
    }
    atomicAdd(&y[(((b * 4 + i) * NN) + n) * NN + m], s);
}

// ---------------------------------------------------------------------------
extern "C" void kernel_launch(void* const* d_in, const int* in_sizes, int n_in,
                              void* d_out, int out_size) {
    const float* image = (const float*)d_in[0];  // (4,256,256)
    const float* x     = (const float*)d_in[1];  // (4,4,256,256)
    const float* W1    = (const float*)d_in[2];  // (16,20,1,3,3)
    const float* b1    = (const float*)d_in[3];  // (16,20)
    const float* W2    = (const float*)d_in[4];  // (16,9,20,3,3)
    const float* b2    = (const float*)d_in[5];  // (16,9)
    float* y = (float*)d_out;                    // (4,4,256,256)

    k_precompute<<<1, 144>>>(W1, b1, W2, b2);

    dim3 g2(NN / TILE, NN / TILE, 4);            // 8 x 8 x 4 = 256 blocks
    k_main<<<g2, 256>>>(image, x, y);

    dim3 g3(16, 16);                             // 16 p-values x 16 pixel chunks
    k_border<<<g3, 256>>>(image, x, W1, b1, W2, b2, y);
}